// round 3
// baseline (speedup 1.0000x reference)
#include <cuda_runtime.h>
#include <cuda_fp16.h>
#include <cstdint>
#include <cstddef>

// ---------------- problem constants ----------------
#define N_TOK  8192
#define D_INF  4096
#define D_OUTF 4096

// GEMM tiling
#define MT   128
#define NT   128
#define BK   64
#define M_TILES 64      // 8192/128
#define N_TILES 32      // 4096/128
#define KTOT    65      // 64 main K-chunks + 1 LoRA chunk
#define NSTAGE  4

#define A_TILE_ELEMS (MT*BK)        // 8192 halves (16 KB)
#define B_TILE_ELEMS (NT*BK)        // 8192 halves (16 KB)
#define A_TILE_BYTES (A_TILE_ELEMS*2)
#define B_TILE_BYTES (B_TILE_ELEMS*2)
#define STAGE_BYTES  (A_TILE_BYTES + 2*B_TILE_BYTES)     // 49152
#define SMEM_TOTAL   (1024 + 1024 + NSTAGE*STAGE_BYTES)  // 198656 < 227KB

// ---------------- scratch (device globals; no cudaMalloc allowed) ----------------
__device__ __align__(1024) __half gA   [(size_t)M_TILES*KTOT*A_TILE_ELEMS];  // x hi (fp16)
__device__ __align__(1024) __half gB_hi[(size_t)N_TILES*KTOT*B_TILE_ELEMS];  // W hi
__device__ __align__(1024) __half gB_lo[(size_t)N_TILES*KTOT*B_TILE_ELEMS];  // W lo
__device__ __align__(1024) float g_interw[N_TOK*32];

// ---------------- PTX helpers (sm_100 baseline only; NO tcgen05) ----------------
__device__ __forceinline__ uint32_t smem_u32(const void* p){
    uint32_t a;
    asm("{ .reg .u64 t; cvta.to.shared.u64 t, %1; cvt.u32.u64 %0, t; }" : "=r"(a) : "l"(p));
    return a;
}
__device__ __forceinline__ uint32_t swz128(uint32_t b){ return b ^ ((b >> 3) & 0x70); }

#define MBARRIER_INIT(addr, cnt) \
    asm volatile("mbarrier.init.shared.b64 [%0], %1;" :: "r"(addr), "r"(cnt) : "memory")
#define MBARRIER_EXPECT_TX(addr, bytes) \
    asm volatile("mbarrier.arrive.expect_tx.shared.b64 _, [%0], %1;" :: "r"(addr), "r"(bytes) : "memory")
#define MBARRIER_ARRIVE(addr) \
    asm volatile("mbarrier.arrive.shared.b64 _, [%0];" :: "r"(addr) : "memory")
#define MBARRIER_WAIT_PARITY(addr, par) do {                                     \
    uint32_t _m = (addr); uint32_t _p = (par); uint32_t _d;                      \
    asm volatile("{\n\t.reg .pred p;\n\t"                                        \
        "mbarrier.try_wait.parity.acquire.cta.shared::cta.b64 p, [%1], %2;\n\t"  \
        "selp.b32 %0, 1, 0, p;\n\t}" : "=r"(_d) : "r"(_m), "r"(_p) : "memory");  \
    if (!_d) {                                                                   \
        asm volatile("{\n\t.reg .pred P1;\n\t"                                   \
        "W_%=:\n\t"                                                              \
        "mbarrier.try_wait.parity.acquire.cta.shared::cta.b64 P1, [%0], %1, 0x989680;\n\t" \
        "@P1 bra.uni D_%=;\n\t"                                                  \
        "bra.uni W_%=;\n\t"                                                      \
        "D_%=:\n\t}" :: "r"(_m), "r"(_p) : "memory");                            \
    }                                                                            \
} while (0)

__device__ __forceinline__ void bulk_g2s(uint32_t dst, const void* src, uint32_t bytes, uint32_t mbar){
    asm volatile("cp.async.bulk.shared::cta.global.mbarrier::complete_tx::bytes [%0], [%1], %2, [%3];"
        :: "r"(dst), "l"(src), "r"(bytes), "r"(mbar) : "memory");
}

#define LDSM_X4(r0, r1, r2, r3, addr) \
    asm volatile("ldmatrix.sync.aligned.m8n8.x4.shared.b16 {%0,%1,%2,%3}, [%4];" \
        : "=r"(r0), "=r"(r1), "=r"(r2), "=r"(r3) : "r"(addr))

#define MMA16816(d, a, b) \
    asm volatile("mma.sync.aligned.m16n8k16.row.col.f32.f16.f16.f32 " \
        "{%0,%1,%2,%3}, {%4,%5,%6,%7}, {%8,%9}, {%0,%1,%2,%3};" \
        : "+f"((d)[0]), "+f"((d)[1]), "+f"((d)[2]), "+f"((d)[3]) \
        : "r"((a)[0]), "r"((a)[1]), "r"((a)[2]), "r"((a)[3]), "r"((b)[0]), "r"((b)[1]))

// ---------------- prep kernels ----------------
// x -> fp16 hi, tiled + SW128-swizzled, in exactly the GEMM's smem tile layout
__global__ void __launch_bounds__(256) conv_x_kernel(const float* __restrict__ x){
    size_t idx = (size_t)blockIdx.x * 256 + threadIdx.x;           // < 8192*4096
    int n = (int)(idx >> 12), k = (int)(idx & 4095);
    float v = x[idx];
    int mt = n >> 7, r = n & 127, kc = k >> 6, c = k & 63;
    size_t tile = (size_t)mt * KTOT + kc;
    uint32_t off = swz128((uint32_t)(r * 128 + c * 2)) >> 1;
    gA[tile * A_TILE_ELEMS + off] = __float2half_rn(v);
}

// W -> fp16 hi/lo split, tiled + swizzled
__global__ void __launch_bounds__(256) split_w_kernel(const float* __restrict__ W){
    size_t idx = (size_t)blockIdx.x * 256 + threadIdx.x;           // < 4096*4096
    int o = (int)(idx >> 12), k = (int)(idx & 4095);
    float v = W[idx];
    __half hi = __float2half_rn(v);
    __half lo = __float2half_rn(v - __half2float(hi));
    int nt = o >> 7, r = o & 127, kc = k >> 6, c = k & 63;
    size_t tile = (size_t)nt * KTOT + kc;
    uint32_t off = swz128((uint32_t)(r * 128 + c * 2)) >> 1;
    gB_hi[tile * B_TILE_ELEMS + off] = hi;
    gB_lo[tile * B_TILE_ELEMS + off] = lo;
}

// interw[n][j] = dot(x[n,:], qa[j,:]) * mask(top_k_weights);  j = e*8+r
__global__ void __launch_bounds__(256) lora_inter_kernel(const float* __restrict__ x,
                                                         const float* __restrict__ qa,
                                                         const float* __restrict__ tkw){
    __shared__ float sqa[32][33];
    __shared__ float sx[64][33];
    int n0  = blockIdx.x * 64;
    int tid = threadIdx.x;
    int r   = tid >> 2;            // 0..63
    int jq  = (tid & 3) * 8;       // 0,8,16,24
    float acc[8] = {0,0,0,0,0,0,0,0};
    for (int k0 = 0; k0 < D_INF; k0 += 32){
        for (int i = tid; i < 32*32; i += 256)
            sqa[i >> 5][i & 31] = qa[(size_t)(i >> 5) * D_INF + k0 + (i & 31)];
        for (int i = tid; i < 64*32; i += 256)
            sx[i >> 5][i & 31] = x[(size_t)(n0 + (i >> 5)) * D_INF + k0 + (i & 31)];
        __syncthreads();
        #pragma unroll
        for (int kk = 0; kk < 32; kk++){
            float xv = sx[r][kk];
            #pragma unroll
            for (int q = 0; q < 8; q++) acc[q] += xv * sqa[jq + q][kk];
        }
        __syncthreads();
    }
    int n = n0 + r;
    #pragma unroll
    for (int q = 0; q < 8; q++){
        int j = jq + q; int e = j >> 3;
        float w = tkw[n * 4 + e];
        w = (fabsf(w) > 1e-6f) ? w : 0.f;
        g_interw[n * 32 + j] = acc[q] * w;
    }
}

// LoRA K-chunk (index 64) for A: cols 0..31 = interw, 32..63 = 0
__global__ void __launch_bounds__(256) pack_a_lora_kernel(){
    int idx = blockIdx.x * 256 + threadIdx.x;     // < 64*8192
    int mt = idx >> 13, rem = idx & 8191;
    int r = rem >> 6, c = rem & 63;
    float v = (c < 32) ? g_interw[(mt * 128 + r) * 32 + c] : 0.f;
    size_t tile = (size_t)mt * KTOT + 64;
    uint32_t off = swz128((uint32_t)(r * 128 + c * 2)) >> 1;
    gA[tile * A_TILE_ELEMS + off] = __float2half_rn(v);
}

// LoRA K-chunk for B: bmat[o][j] = 0.1 * qb[e,o,r] * sf[e,o]
__global__ void __launch_bounds__(256) pack_b_lora_kernel(const float* __restrict__ qb,
                                                          const float* __restrict__ sf){
    int idx = blockIdx.x * 256 + threadIdx.x;     // < 32*8192
    int nt = idx >> 13, rem = idx & 8191;
    int r = rem >> 6, c = rem & 63;
    int o = nt * 128 + r;
    float v = 0.f;
    if (c < 32){
        int e = c >> 3, rr = c & 7;
        v = 0.1f * qb[((size_t)e * D_OUTF + o) * 8 + rr] * sf[(size_t)e * D_OUTF + o];
    }
    __half hi = __float2half_rn(v);
    __half lo = __float2half_rn(v - __half2float(hi));
    size_t tile = (size_t)nt * KTOT + 64;
    uint32_t off = swz128((uint32_t)(r * 128 + c * 2)) >> 1;
    gB_hi[tile * B_TILE_ELEMS + off] = hi;
    gB_lo[tile * B_TILE_ELEMS + off] = lo;
}

// ---------------- main GEMM: mma.sync fp16, W split (2 accumulating passes) ----------------
__global__ void __launch_bounds__(256, 1) gemm_hmma_kernel(float* __restrict__ out){
    extern __shared__ char smem_raw[];
    uint32_t raw = smem_u32(smem_raw);
    uint32_t sb  = (raw + 1023u) & ~1023u;        // barrier block (64B used)
    uint32_t st0 = sb + 1024;                     // stage 0

    int tid = threadIdx.x, wid = tid >> 5, lane = tid & 31;
    int warp_m = wid & 3, warp_n = wid >> 2;      // 4x2 warp grid (32 rows x 64 cols each)
    int bid = blockIdx.x;
    int nt = bid >> 6, mt = bid & 63;             // panel raster: 64 M-tiles share B panel in L2

    const __half* pA  = gA    + (size_t)mt * (KTOT * A_TILE_ELEMS);
    const __half* pBh = gB_hi + (size_t)nt * (KTOT * B_TILE_ELEMS);
    const __half* pBl = gB_lo + (size_t)nt * (KTOT * B_TILE_ELEMS);

    // barriers: full[0..3] at sb+0..31, empty[0..3] at sb+32..63
    if (tid == 0){
        #pragma unroll
        for (int s = 0; s < NSTAGE; s++){
            MBARRIER_INIT(sb + s * 8, 1);
            MBARRIER_INIT(sb + 32 + s * 8, 256);
        }
        asm volatile("fence.proxy.async.shared::cta;" ::: "memory");
    }
    __syncthreads();

    if (tid == 0){
        #pragma unroll
        for (int s = 0; s < NSTAGE; s++){
            uint32_t st = st0 + s * STAGE_BYTES;
            uint32_t mbf = sb + s * 8;
            MBARRIER_EXPECT_TX(mbf, STAGE_BYTES);
            bulk_g2s(st,                 pA  + (size_t)s * A_TILE_ELEMS, A_TILE_BYTES, mbf);
            bulk_g2s(st + A_TILE_BYTES,  pBh + (size_t)s * B_TILE_ELEMS, B_TILE_BYTES, mbf);
            bulk_g2s(st + A_TILE_BYTES + B_TILE_BYTES,
                                          pBl + (size_t)s * B_TILE_ELEMS, B_TILE_BYTES, mbf);
        }
    }

    // ldmatrix per-lane address precomputation
    int lm = (lane >> 3) & 1;                     // row-half select within x4
    int lr = lane & 7;
    uint32_t g16 = (lane & 16);                   // k 16B-group select (0 or 16)
    uint32_t xm  = (uint32_t)(lr << 4);           // swizzle xor mask ((row&7)<<4)
    uint32_t aRow[2], bRow[4];
    #pragma unroll
    for (int mi = 0; mi < 2; mi++)
        aRow[mi] = (uint32_t)((warp_m * 32 + mi * 16 + lm * 8 + lr) * 128);
    #pragma unroll
    for (int nj = 0; nj < 4; nj++)
        bRow[nj] = (uint32_t)((warp_n * 64 + nj * 16 + lm * 8 + lr) * 128);

    float acc[2][8][4];
    #pragma unroll
    for (int mi = 0; mi < 2; mi++)
        #pragma unroll
        for (int ni = 0; ni < 8; ni++)
            #pragma unroll
            for (int q = 0; q < 4; q++) acc[mi][ni][q] = 0.f;

    for (int i = 0; i < KTOT; i++){
        int s  = i & (NSTAGE - 1);
        int ph = (i >> 2) & 1;
        MBARRIER_WAIT_PARITY(sb + s * 8, ph);

        uint32_t stg = st0 + s * STAGE_BYTES;
        uint32_t sA  = stg;
        uint32_t sBh = stg + A_TILE_BYTES;
        uint32_t sBl = stg + A_TILE_BYTES + B_TILE_BYTES;

        #pragma unroll
        for (int ks = 0; ks < 4; ks++){
            uint32_t kb = (uint32_t)(ks * 32);
            uint32_t koff = (kb + g16) ^ xm;
            uint32_t a[2][4], b[8][2];
            #pragma unroll
            for (int mi = 0; mi < 2; mi++)
                LDSM_X4(a[mi][0], a[mi][1], a[mi][2], a[mi][3], sA + aRow[mi] + koff);
            // pass 1: B hi
            #pragma unroll
            for (int nj = 0; nj < 4; nj++){
                uint32_t t0, t1, t2, t3;
                LDSM_X4(t0, t1, t2, t3, sBh + bRow[nj] + koff);
                b[2*nj][0] = t0; b[2*nj][1] = t2;
                b[2*nj+1][0] = t1; b[2*nj+1][1] = t3;
            }
            #pragma unroll
            for (int mi = 0; mi < 2; mi++)
                #pragma unroll
                for (int ni = 0; ni < 8; ni++)
                    MMA16816(acc[mi][ni], a[mi], b[ni]);
            // pass 2: B lo
            #pragma unroll
            for (int nj = 0; nj < 4; nj++){
                uint32_t t0, t1, t2, t3;
                LDSM_X4(t0, t1, t2, t3, sBl + bRow[nj] + koff);
                b[2*nj][0] = t0; b[2*nj][1] = t2;
                b[2*nj+1][0] = t1; b[2*nj+1][1] = t3;
            }
            #pragma unroll
            for (int mi = 0; mi < 2; mi++)
                #pragma unroll
                for (int ni = 0; ni < 8; ni++)
                    MMA16816(acc[mi][ni], a[mi], b[ni]);
        }

        MBARRIER_ARRIVE(sb + 32 + s * 8);
        if (tid == 0 && i + NSTAGE < KTOT){
            MBARRIER_WAIT_PARITY(sb + 32 + s * 8, ph);
            int c = i + NSTAGE;
            uint32_t mbf = sb + s * 8;
            MBARRIER_EXPECT_TX(mbf, STAGE_BYTES);
            bulk_g2s(stg,                 pA  + (size_t)c * A_TILE_ELEMS, A_TILE_BYTES, mbf);
            bulk_g2s(stg + A_TILE_BYTES,  pBh + (size_t)c * B_TILE_ELEMS, B_TILE_BYTES, mbf);
            bulk_g2s(stg + A_TILE_BYTES + B_TILE_BYTES,
                                           pBl + (size_t)c * B_TILE_ELEMS, B_TILE_BYTES, mbf);
        }
    }

    // epilogue: direct STG.64 from accumulators
    int rowbase = mt * MT + warp_m * 32;
    int colbase = nt * NT + warp_n * 64;
    int rlo = lane >> 2, cq = (lane & 3) * 2;
    #pragma unroll
    for (int mi = 0; mi < 2; mi++){
        #pragma unroll
        for (int ni = 0; ni < 8; ni++){
            int r0 = rowbase + mi * 16 + rlo;
            int c  = colbase + ni * 8 + cq;
            float2 v0 = make_float2(acc[mi][ni][0], acc[mi][ni][1]);
            float2 v1 = make_float2(acc[mi][ni][2], acc[mi][ni][3]);
            *reinterpret_cast<float2*>(&out[(size_t)r0 * D_OUTF + c])       = v0;
            *reinterpret_cast<float2*>(&out[(size_t)(r0 + 8) * D_OUTF + c]) = v1;
        }
    }
}

// ---------------- launch ----------------
extern "C" void kernel_launch(void* const* d_in, const int* in_sizes, int n_in,
                              void* d_out, int out_size){
    const float* x   = (const float*)d_in[0];   // [8192, 4096]
    const float* tkw = (const float*)d_in[1];   // [8192, 4]
    const float* W   = (const float*)d_in[2];   // [4096, 4096]
    const float* qa  = (const float*)d_in[3];   // [4, 8, 4096]
    const float* qb  = (const float*)d_in[4];   // [4, 4096, 8]
    const float* sf  = (const float*)d_in[5];   // [4, 4096]
    float* out = (float*)d_out;                 // [8192, 4096]

    conv_x_kernel<<<(N_TOK * D_INF) / 256, 256>>>(x);
    split_w_kernel<<<(D_OUTF * D_INF) / 256, 256>>>(W);
    lora_inter_kernel<<<N_TOK / 64, 256>>>(x, qa, tkw);
    pack_a_lora_kernel<<<(M_TILES * A_TILE_ELEMS) / 256, 256>>>();
    pack_b_lora_kernel<<<(N_TILES * B_TILE_ELEMS) / 256, 256>>>(qb, sf);

    cudaFuncSetAttribute(gemm_hmma_kernel,
                         cudaFuncAttributeMaxDynamicSharedMemorySize, SMEM_TOTAL);
    gemm_hmma_kernel<<<M_TILES * N_TILES, 256, SMEM_TOTAL>>>(out);
}

// round 4
// speedup vs baseline: 1.3971x; 1.3971x over previous
#include <cuda_runtime.h>
#include <cuda_fp16.h>
#include <cstdint>
#include <cstddef>

// ---------------- problem constants ----------------
#define N_TOK  8192
#define D_INF  4096
#define D_OUTF 4096

// GEMM tiling
#define MT   128
#define NT   128
#define BK   64
#define M_TILES 64      // 8192/128
#define N_TILES 32      // 4096/128
#define KTOT    65      // 64 main K-chunks + 1 LoRA chunk
#define NSTAGE  6

#define A_TILE_ELEMS (MT*BK)        // 8192 halves (16 KB)
#define B_TILE_ELEMS (NT*BK)        // 8192 halves (16 KB)
#define A_TILE_BYTES (A_TILE_ELEMS*2)
#define B_TILE_BYTES (B_TILE_ELEMS*2)
#define STAGE_BYTES  (A_TILE_BYTES + B_TILE_BYTES)       // 32768
#define SMEM_TOTAL   (1024 + 1024 + NSTAGE*STAGE_BYTES)  // 198656 < 227KB

// ---------------- scratch (device globals; no cudaMalloc allowed) ----------------
__device__ __align__(1024) __half gA[(size_t)M_TILES*KTOT*A_TILE_ELEMS];  // x (fp16)
__device__ __align__(1024) __half gB[(size_t)N_TILES*KTOT*B_TILE_ELEMS];  // W (fp16)
__device__ __align__(1024) float g_interw[N_TOK*32];

// ---------------- PTX helpers (sm_100 baseline only) ----------------
__device__ __forceinline__ uint32_t smem_u32(const void* p){
    uint32_t a;
    asm("{ .reg .u64 t; cvta.to.shared.u64 t, %1; cvt.u32.u64 %0, t; }" : "=r"(a) : "l"(p));
    return a;
}
__device__ __forceinline__ uint32_t swz128(uint32_t b){ return b ^ ((b >> 3) & 0x70); }

#define MBARRIER_INIT(addr, cnt) \
    asm volatile("mbarrier.init.shared.b64 [%0], %1;" :: "r"(addr), "r"(cnt) : "memory")
#define MBARRIER_EXPECT_TX(addr, bytes) \
    asm volatile("mbarrier.arrive.expect_tx.shared.b64 _, [%0], %1;" :: "r"(addr), "r"(bytes) : "memory")
#define MBARRIER_ARRIVE(addr) \
    asm volatile("mbarrier.arrive.shared.b64 _, [%0];" :: "r"(addr) : "memory")
#define MBARRIER_WAIT_PARITY(addr, par) do {                                     \
    uint32_t _m = (addr); uint32_t _p = (par); uint32_t _d;                      \
    asm volatile("{\n\t.reg .pred p;\n\t"                                        \
        "mbarrier.try_wait.parity.acquire.cta.shared::cta.b64 p, [%1], %2;\n\t"  \
        "selp.b32 %0, 1, 0, p;\n\t}" : "=r"(_d) : "r"(_m), "r"(_p) : "memory");  \
    if (!_d) {                                                                   \
        asm volatile("{\n\t.reg .pred P1;\n\t"                                   \
        "W_%=:\n\t"                                                              \
        "mbarrier.try_wait.parity.acquire.cta.shared::cta.b64 P1, [%0], %1, 0x989680;\n\t" \
        "@P1 bra.uni D_%=;\n\t"                                                  \
        "bra.uni W_%=;\n\t"                                                      \
        "D_%=:\n\t}" :: "r"(_m), "r"(_p) : "memory");                            \
    }                                                                            \
} while (0)

__device__ __forceinline__ void bulk_g2s(uint32_t dst, const void* src, uint32_t bytes, uint32_t mbar){
    asm volatile("cp.async.bulk.shared::cta.global.mbarrier::complete_tx::bytes [%0], [%1], %2, [%3];"
        :: "r"(dst), "l"(src), "r"(bytes), "r"(mbar) : "memory");
}

#define LDSM_X4(r0, r1, r2, r3, addr) \
    asm volatile("ldmatrix.sync.aligned.m8n8.x4.shared.b16 {%0,%1,%2,%3}, [%4];" \
        : "=r"(r0), "=r"(r1), "=r"(r2), "=r"(r3) : "r"(addr))

#define MMA16816(d, a, b) \
    asm volatile("mma.sync.aligned.m16n8k16.row.col.f32.f16.f16.f32 " \
        "{%0,%1,%2,%3}, {%4,%5,%6,%7}, {%8,%9}, {%0,%1,%2,%3};" \
        : "+f"((d)[0]), "+f"((d)[1]), "+f"((d)[2]), "+f"((d)[3]) \
        : "r"((a)[0]), "r"((a)[1]), "r"((a)[2]), "r"((a)[3]), "r"((b)[0]), "r"((b)[1]))

// ---------------- prep kernels ----------------
// x -> fp16, tiled + SW128-swizzled, in exactly the GEMM's smem tile layout
__global__ void __launch_bounds__(256) conv_x_kernel(const float* __restrict__ x){
    size_t idx = (size_t)blockIdx.x * 256 + threadIdx.x;           // < 8192*4096
    int n = (int)(idx >> 12), k = (int)(idx & 4095);
    float v = x[idx];
    int mt = n >> 7, r = n & 127, kc = k >> 6, c = k & 63;
    size_t tile = (size_t)mt * KTOT + kc;
    uint32_t off = swz128((uint32_t)(r * 128 + c * 2)) >> 1;
    gA[tile * A_TILE_ELEMS + off] = __float2half_rn(v);
}

// W -> fp16, tiled + swizzled
__global__ void __launch_bounds__(256) conv_w_kernel(const float* __restrict__ W){
    size_t idx = (size_t)blockIdx.x * 256 + threadIdx.x;           // < 4096*4096
    int o = (int)(idx >> 12), k = (int)(idx & 4095);
    float v = W[idx];
    int nt = o >> 7, r = o & 127, kc = k >> 6, c = k & 63;
    size_t tile = (size_t)nt * KTOT + kc;
    uint32_t off = swz128((uint32_t)(r * 128 + c * 2)) >> 1;
    gB[tile * B_TILE_ELEMS + off] = __float2half_rn(v);
}

// interw[n][j] = dot(x[n,:], qa[j,:]) * mask(top_k_weights);  j = e*8+r
__global__ void __launch_bounds__(256) lora_inter_kernel(const float* __restrict__ x,
                                                         const float* __restrict__ qa,
                                                         const float* __restrict__ tkw){
    __shared__ float sqa[32][33];
    __shared__ float sx[64][33];
    int n0  = blockIdx.x * 64;
    int tid = threadIdx.x;
    int r   = tid >> 2;            // 0..63
    int jq  = (tid & 3) * 8;       // 0,8,16,24
    float acc[8] = {0,0,0,0,0,0,0,0};
    for (int k0 = 0; k0 < D_INF; k0 += 32){
        for (int i = tid; i < 32*32; i += 256)
            sqa[i >> 5][i & 31] = qa[(size_t)(i >> 5) * D_INF + k0 + (i & 31)];
        for (int i = tid; i < 64*32; i += 256)
            sx[i >> 5][i & 31] = x[(size_t)(n0 + (i >> 5)) * D_INF + k0 + (i & 31)];
        __syncthreads();
        #pragma unroll
        for (int kk = 0; kk < 32; kk++){
            float xv = sx[r][kk];
            #pragma unroll
            for (int q = 0; q < 8; q++) acc[q] += xv * sqa[jq + q][kk];
        }
        __syncthreads();
    }
    int n = n0 + r;
    #pragma unroll
    for (int q = 0; q < 8; q++){
        int j = jq + q; int e = j >> 3;
        float w = tkw[n * 4 + e];
        w = (fabsf(w) > 1e-6f) ? w : 0.f;
        g_interw[n * 32 + j] = acc[q] * w;
    }
}

// LoRA K-chunk (index 64) for A: cols 0..31 = interw, 32..63 = 0
__global__ void __launch_bounds__(256) pack_a_lora_kernel(){
    int idx = blockIdx.x * 256 + threadIdx.x;     // < 64*8192
    int mt = idx >> 13, rem = idx & 8191;
    int r = rem >> 6, c = rem & 63;
    float v = (c < 32) ? g_interw[(mt * 128 + r) * 32 + c] : 0.f;
    size_t tile = (size_t)mt * KTOT + 64;
    uint32_t off = swz128((uint32_t)(r * 128 + c * 2)) >> 1;
    gA[tile * A_TILE_ELEMS + off] = __float2half_rn(v);
}

// LoRA K-chunk for B: bmat[o][j] = 0.1 * qb[e,o,r] * sf[e,o]
__global__ void __launch_bounds__(256) pack_b_lora_kernel(const float* __restrict__ qb,
                                                          const float* __restrict__ sf){
    int idx = blockIdx.x * 256 + threadIdx.x;     // < 32*8192
    int nt = idx >> 13, rem = idx & 8191;
    int r = rem >> 6, c = rem & 63;
    int o = nt * 128 + r;
    float v = 0.f;
    if (c < 32){
        int e = c >> 3, rr = c & 7;
        v = 0.1f * qb[((size_t)e * D_OUTF + o) * 8 + rr] * sf[(size_t)e * D_OUTF + o];
    }
    size_t tile = (size_t)nt * KTOT + 64;
    uint32_t off = swz128((uint32_t)(r * 128 + c * 2)) >> 1;
    gB[tile * B_TILE_ELEMS + off] = __float2half_rn(v);
}

// ---------------- main GEMM: mma.sync fp16, single pass, 6-stage pipeline ----------------
__global__ void __launch_bounds__(256, 1) gemm_hmma_kernel(float* __restrict__ out){
    extern __shared__ char smem_raw[];
    uint32_t raw = smem_u32(smem_raw);
    uint32_t sb  = (raw + 1023u) & ~1023u;        // barrier block
    uint32_t st0 = sb + 1024;                     // stage 0

    int tid = threadIdx.x, wid = tid >> 5, lane = tid & 31;
    int warp_m = wid & 3, warp_n = wid >> 2;      // 4x2 warp grid (32 rows x 64 cols each)
    int bid = blockIdx.x;
    int nt = bid >> 6, mt = bid & 63;             // panel raster: 64 M-tiles share B panel in L2

    const __half* pA = gA + (size_t)mt * (KTOT * A_TILE_ELEMS);
    const __half* pB = gB + (size_t)nt * (KTOT * B_TILE_ELEMS);

    // barriers: full[s] at sb + s*8, empty[s] at sb + 64 + s*8
    if (tid == 0){
        #pragma unroll
        for (int s = 0; s < NSTAGE; s++){
            MBARRIER_INIT(sb + s * 8, 1);
            MBARRIER_INIT(sb + 64 + s * 8, 256);
        }
        asm volatile("fence.proxy.async.shared::cta;" ::: "memory");
    }
    __syncthreads();

    if (tid == 0){
        #pragma unroll
        for (int s = 0; s < NSTAGE; s++){
            uint32_t st = st0 + s * STAGE_BYTES;
            uint32_t mbf = sb + s * 8;
            MBARRIER_EXPECT_TX(mbf, STAGE_BYTES);
            bulk_g2s(st,                pA + (size_t)s * A_TILE_ELEMS, A_TILE_BYTES, mbf);
            bulk_g2s(st + A_TILE_BYTES, pB + (size_t)s * B_TILE_ELEMS, B_TILE_BYTES, mbf);
        }
    }

    // ldmatrix per-lane address precomputation
    int lm = (lane >> 3) & 1;                     // row-half select within x4
    int lr = lane & 7;
    uint32_t g16 = (lane & 16);                   // k 16B-group select (0 or 16)
    uint32_t xm  = (uint32_t)(lr << 4);           // swizzle xor mask ((row&7)<<4)
    uint32_t aRow[2], bRow[4];
    #pragma unroll
    for (int mi = 0; mi < 2; mi++)
        aRow[mi] = (uint32_t)((warp_m * 32 + mi * 16 + lm * 8 + lr) * 128);
    #pragma unroll
    for (int nj = 0; nj < 4; nj++)
        bRow[nj] = (uint32_t)((warp_n * 64 + nj * 16 + lm * 8 + lr) * 128);

    float acc[2][8][4];
    #pragma unroll
    for (int mi = 0; mi < 2; mi++)
        #pragma unroll
        for (int ni = 0; ni < 8; ni++)
            #pragma unroll
            for (int q = 0; q < 4; q++) acc[mi][ni][q] = 0.f;

    int s = 0, ph = 0;
    for (int i = 0; i < KTOT; i++){
        MBARRIER_WAIT_PARITY(sb + s * 8, ph);

        uint32_t stg = st0 + s * STAGE_BYTES;
        uint32_t sA  = stg;
        uint32_t sB  = stg + A_TILE_BYTES;

        #pragma unroll
        for (int ks = 0; ks < 4; ks++){
            uint32_t koff = ((uint32_t)(ks * 32) + g16) ^ xm;
            uint32_t a[2][4], b[8][2];
            #pragma unroll
            for (int mi = 0; mi < 2; mi++)
                LDSM_X4(a[mi][0], a[mi][1], a[mi][2], a[mi][3], sA + aRow[mi] + koff);
            #pragma unroll
            for (int nj = 0; nj < 4; nj++){
                uint32_t t0, t1, t2, t3;
                LDSM_X4(t0, t1, t2, t3, sB + bRow[nj] + koff);
                b[2*nj][0] = t0; b[2*nj][1] = t2;
                b[2*nj+1][0] = t1; b[2*nj+1][1] = t3;
            }
            #pragma unroll
            for (int mi = 0; mi < 2; mi++)
                #pragma unroll
                for (int ni = 0; ni < 8; ni++)
                    MMA16816(acc[mi][ni], a[mi], b[ni]);
        }

        MBARRIER_ARRIVE(sb + 64 + s * 8);
        if (tid == 0 && i + NSTAGE < KTOT){
            MBARRIER_WAIT_PARITY(sb + 64 + s * 8, ph);
            int c = i + NSTAGE;
            uint32_t mbf = sb + s * 8;
            MBARRIER_EXPECT_TX(mbf, STAGE_BYTES);
            bulk_g2s(stg,                pA + (size_t)c * A_TILE_ELEMS, A_TILE_BYTES, mbf);
            bulk_g2s(stg + A_TILE_BYTES, pB + (size_t)c * B_TILE_ELEMS, B_TILE_BYTES, mbf);
        }
        if (++s == NSTAGE){ s = 0; ph ^= 1; }
    }

    // epilogue: direct STG.64 from accumulators
    int rowbase = mt * MT + warp_m * 32;
    int colbase = nt * NT + warp_n * 64;
    int rlo = lane >> 2, cq = (lane & 3) * 2;
    #pragma unroll
    for (int mi = 0; mi < 2; mi++){
        #pragma unroll
        for (int ni = 0; ni < 8; ni++){
            int r0 = rowbase + mi * 16 + rlo;
            int c  = colbase + ni * 8 + cq;
            float2 v0 = make_float2(acc[mi][ni][0], acc[mi][ni][1]);
            float2 v1 = make_float2(acc[mi][ni][2], acc[mi][ni][3]);
            *reinterpret_cast<float2*>(&out[(size_t)r0 * D_OUTF + c])       = v0;
            *reinterpret_cast<float2*>(&out[(size_t)(r0 + 8) * D_OUTF + c]) = v1;
        }
    }
}

// ---------------- launch ----------------
extern "C" void kernel_launch(void* const* d_in, const int* in_sizes, int n_in,
                              void* d_out, int out_size){
    const float* x   = (const float*)d_in[0];   // [8192, 4096]
    const float* tkw = (const float*)d_in[1];   // [8192, 4]
    const float* W   = (const float*)d_in[2];   // [4096, 4096]
    const float* qa  = (const float*)d_in[3];   // [4, 8, 4096]
    const float* qb  = (const float*)d_in[4];   // [4, 4096, 8]
    const float* sf  = (const float*)d_in[5];   // [4, 4096]
    float* out = (float*)d_out;                 // [8192, 4096]

    conv_x_kernel<<<(N_TOK * D_INF) / 256, 256>>>(x);
    conv_w_kernel<<<(D_OUTF * D_INF) / 256, 256>>>(W);
    lora_inter_kernel<<<N_TOK / 64, 256>>>(x, qa, tkw);
    pack_a_lora_kernel<<<(M_TILES * A_TILE_ELEMS) / 256, 256>>>();
    pack_b_lora_kernel<<<(N_TILES * B_TILE_ELEMS) / 256, 256>>>(qb, sf);

    cudaFuncSetAttribute(gemm_hmma_kernel,
                         cudaFuncAttributeMaxDynamicSharedMemorySize, SMEM_TOTAL);
    gemm_hmma_kernel<<<M_TILES * N_TILES, 256, SMEM_TOTAL>>>(out);
}

// round 6
// speedup vs baseline: 1.4682x; 1.0509x over previous
#include <cuda_runtime.h>
#include <cuda_fp16.h>
#include <cstdint>
#include <cstddef>

// ---------------- problem constants ----------------
#define N_TOK  8192
#define D_INF  4096
#define D_OUTF 4096

// GEMM tiling
#define MT   128
#define NT   128
#define BK   64
#define M_TILES 64      // 8192/128
#define N_TILES 32      // 4096/128
#define KTOT    65      // 64 main K-chunks + 1 LoRA chunk
#define NSTAGE  3

#define A_TILE_ELEMS (MT*BK)        // 8192 halves (16 KB)
#define B_TILE_ELEMS (NT*BK)        // 8192 halves (16 KB)
#define A_TILE_BYTES (A_TILE_ELEMS*2)
#define B_TILE_BYTES (B_TILE_ELEMS*2)
#define STAGE_BYTES  (A_TILE_BYTES + B_TILE_BYTES)       // 32768
#define SMEM_TOTAL   (1024 + 1024 + NSTAGE*STAGE_BYTES)  // 100352 -> 2 CTAs/SM

// ---------------- scratch (device globals; no cudaMalloc allowed) ----------------
__device__ __align__(1024) __half gA[(size_t)M_TILES*KTOT*A_TILE_ELEMS];  // x (fp16)
__device__ __align__(1024) __half gB[(size_t)N_TILES*KTOT*B_TILE_ELEMS];  // W (fp16)
__device__ __align__(1024) float g_interw[N_TOK*32];

// ---------------- PTX helpers (sm_100 baseline only) ----------------
__device__ __forceinline__ uint32_t smem_u32(const void* p){
    uint32_t a;
    asm("{ .reg .u64 t; cvta.to.shared.u64 t, %1; cvt.u32.u64 %0, t; }" : "=r"(a) : "l"(p));
    return a;
}
__device__ __forceinline__ uint32_t swz128(uint32_t b){ return b ^ ((b >> 3) & 0x70); }

#define MBARRIER_INIT(addr, cnt) \
    asm volatile("mbarrier.init.shared.b64 [%0], %1;" :: "r"(addr), "r"(cnt) : "memory")
#define MBARRIER_EXPECT_TX(addr, bytes) \
    asm volatile("mbarrier.arrive.expect_tx.shared.b64 _, [%0], %1;" :: "r"(addr), "r"(bytes) : "memory")
#define MBARRIER_ARRIVE(addr) \
    asm volatile("mbarrier.arrive.shared.b64 _, [%0];" :: "r"(addr) : "memory")
#define MBARRIER_WAIT_PARITY(addr, par) do {                                     \
    uint32_t _m = (addr); uint32_t _p = (par); uint32_t _d;                      \
    asm volatile("{\n\t.reg .pred p;\n\t"                                        \
        "mbarrier.try_wait.parity.acquire.cta.shared::cta.b64 p, [%1], %2;\n\t"  \
        "selp.b32 %0, 1, 0, p;\n\t}" : "=r"(_d) : "r"(_m), "r"(_p) : "memory");  \
    if (!_d) {                                                                   \
        asm volatile("{\n\t.reg .pred P1;\n\t"                                   \
        "W_%=:\n\t"                                                              \
        "mbarrier.try_wait.parity.acquire.cta.shared::cta.b64 P1, [%0], %1, 0x989680;\n\t" \
        "@P1 bra.uni D_%=;\n\t"                                                  \
        "bra.uni W_%=;\n\t"                                                      \
        "D_%=:\n\t}" :: "r"(_m), "r"(_p) : "memory");                            \
    }                                                                            \
} while (0)

__device__ __forceinline__ void bulk_g2s(uint32_t dst, const void* src, uint32_t bytes, uint32_t mbar){
    asm volatile("cp.async.bulk.shared::cta.global.mbarrier::complete_tx::bytes [%0], [%1], %2, [%3];"
        :: "r"(dst), "l"(src), "r"(bytes), "r"(mbar) : "memory");
}

#define LDSM_X4(r0, r1, r2, r3, addr) \
    asm volatile("ldmatrix.sync.aligned.m8n8.x4.shared.b16 {%0,%1,%2,%3}, [%4];" \
        : "=r"(r0), "=r"(r1), "=r"(r2), "=r"(r3) : "r"(addr))

#define MMA16816(d, a, b) \
    asm volatile("mma.sync.aligned.m16n8k16.row.col.f32.f16.f16.f32 " \
        "{%0,%1,%2,%3}, {%4,%5,%6,%7}, {%8,%9}, {%0,%1,%2,%3};" \
        : "+f"((d)[0]), "+f"((d)[1]), "+f"((d)[2]), "+f"((d)[3]) \
        : "r"((a)[0]), "r"((a)[1]), "r"((a)[2]), "r"((a)[3]), "r"((b)[0]), "r"((b)[1]))

// ---------------- prep kernels ----------------
__global__ void __launch_bounds__(256) conv_x_kernel(const float* __restrict__ x){
    size_t idx = (size_t)blockIdx.x * 256 + threadIdx.x;           // < 8192*4096
    int n = (int)(idx >> 12), k = (int)(idx & 4095);
    float v = x[idx];
    int mt = n >> 7, r = n & 127, kc = k >> 6, c = k & 63;
    size_t tile = (size_t)mt * KTOT + kc;
    uint32_t off = swz128((uint32_t)(r * 128 + c * 2)) >> 1;
    gA[tile * A_TILE_ELEMS + off] = __float2half_rn(v);
}

__global__ void __launch_bounds__(256) conv_w_kernel(const float* __restrict__ W){
    size_t idx = (size_t)blockIdx.x * 256 + threadIdx.x;           // < 4096*4096
    int o = (int)(idx >> 12), k = (int)(idx & 4095);
    float v = W[idx];
    int nt = o >> 7, r = o & 127, kc = k >> 6, c = k & 63;
    size_t tile = (size_t)nt * KTOT + kc;
    uint32_t off = swz128((uint32_t)(r * 128 + c * 2)) >> 1;
    gB[tile * B_TILE_ELEMS + off] = __float2half_rn(v);
}

// interw[n][j] = dot(x[n,:], qa[j,:]) * mask(top_k_weights);  j = e*8+r
__global__ void __launch_bounds__(256) lora_inter_kernel(const float* __restrict__ x,
                                                         const float* __restrict__ qa,
                                                         const float* __restrict__ tkw){
    __shared__ float sqa[32][33];
    __shared__ float sx[64][33];
    int n0  = blockIdx.x * 64;
    int tid = threadIdx.x;
    int r   = tid >> 2;            // 0..63
    int jq  = (tid & 3) * 8;       // 0,8,16,24
    float acc[8] = {0,0,0,0,0,0,0,0};
    for (int k0 = 0; k0 < D_INF; k0 += 32){
        for (int i = tid; i < 32*32; i += 256)
            sqa[i >> 5][i & 31] = qa[(size_t)(i >> 5) * D_INF + k0 + (i & 31)];
        for (int i = tid; i < 64*32; i += 256)
            sx[i >> 5][i & 31] = x[(size_t)(n0 + (i >> 5)) * D_INF + k0 + (i & 31)];
        __syncthreads();
        #pragma unroll
        for (int kk = 0; kk < 32; kk++){
            float xv = sx[r][kk];
            #pragma unroll
            for (int q = 0; q < 8; q++) acc[q] += xv * sqa[jq + q][kk];
        }
        __syncthreads();
    }
    int n = n0 + r;
    #pragma unroll
    for (int q = 0; q < 8; q++){
        int j = jq + q; int e = j >> 3;
        float w = tkw[n * 4 + e];
        w = (fabsf(w) > 1e-6f) ? w : 0.f;
        g_interw[n * 32 + j] = acc[q] * w;
    }
}

// LoRA K-chunk (index 64) for A: cols 0..31 = interw, 32..63 = 0
__global__ void __launch_bounds__(256) pack_a_lora_kernel(){
    int idx = blockIdx.x * 256 + threadIdx.x;     // < 64*8192
    int mt = idx >> 13, rem = idx & 8191;
    int r = rem >> 6, c = rem & 63;
    float v = (c < 32) ? g_interw[(mt * 128 + r) * 32 + c] : 0.f;
    size_t tile = (size_t)mt * KTOT + 64;
    uint32_t off = swz128((uint32_t)(r * 128 + c * 2)) >> 1;
    gA[tile * A_TILE_ELEMS + off] = __float2half_rn(v);
}

// LoRA K-chunk for B: bmat[o][j] = 0.1 * qb[e,o,r] * sf[e,o]
__global__ void __launch_bounds__(256) pack_b_lora_kernel(const float* __restrict__ qb,
                                                          const float* __restrict__ sf){
    int idx = blockIdx.x * 256 + threadIdx.x;     // < 32*8192
    int nt = idx >> 13, rem = idx & 8191;
    int r = rem >> 6, c = rem & 63;
    int o = nt * 128 + r;
    float v = 0.f;
    if (c < 32){
        int e = c >> 3, rr = c & 7;
        v = 0.1f * qb[((size_t)e * D_OUTF + o) * 8 + rr] * sf[(size_t)e * D_OUTF + o];
    }
    size_t tile = (size_t)nt * KTOT + 64;
    uint32_t off = swz128((uint32_t)(r * 128 + c * 2)) >> 1;
    gB[tile * B_TILE_ELEMS + off] = __float2half_rn(v);
}

// ---------------- main GEMM: mma.sync fp16, 3-stage pipeline, 2 CTAs/SM ----------------
__global__ void __launch_bounds__(256, 2) gemm_hmma_kernel(float* __restrict__ out){
    extern __shared__ char smem_raw[];
    uint32_t raw = smem_u32(smem_raw);
    uint32_t sb  = (raw + 1023u) & ~1023u;        // barrier block
    uint32_t st0 = sb + 1024;                     // stage 0

    int tid = threadIdx.x, wid = tid >> 5, lane = tid & 31;
    int warp_m = wid & 3, warp_n = wid >> 2;      // 4x2 warp grid (32 rows x 64 cols each)
    int bid = blockIdx.x;
    int nt = bid >> 6, mt = bid & 63;             // panel raster: 64 M-tiles share B panel in L2

    const __half* pA = gA + (size_t)mt * (KTOT * A_TILE_ELEMS);
    const __half* pB = gB + (size_t)nt * (KTOT * B_TILE_ELEMS);

    // barriers: full[s] at sb + s*8, empty[s] at sb + 64 + s*8
    if (tid == 0){
        #pragma unroll
        for (int s = 0; s < NSTAGE; s++){
            MBARRIER_INIT(sb + s * 8, 1);
            MBARRIER_INIT(sb + 64 + s * 8, 256);
        }
        asm volatile("fence.proxy.async.shared::cta;" ::: "memory");
    }
    __syncthreads();

    if (tid == 0){
        #pragma unroll
        for (int s = 0; s < NSTAGE; s++){
            uint32_t st = st0 + s * STAGE_BYTES;
            uint32_t mbf = sb + s * 8;
            MBARRIER_EXPECT_TX(mbf, STAGE_BYTES);
            bulk_g2s(st,                pA + (size_t)s * A_TILE_ELEMS, A_TILE_BYTES, mbf);
            bulk_g2s(st + A_TILE_BYTES, pB + (size_t)s * B_TILE_ELEMS, B_TILE_BYTES, mbf);
        }
    }

    // ldmatrix per-lane address precomputation
    int lm = (lane >> 3) & 1;                     // row-half select within x4
    int lr = lane & 7;
    uint32_t g16 = (lane & 16);                   // k 16B-group select (0 or 16)
    uint32_t xm  = (uint32_t)(lr << 4);           // swizzle xor mask ((row&7)<<4)
    uint32_t aRow[2], bRow[4];
    #pragma unroll
    for (int mi = 0; mi < 2; mi++)
        aRow[mi] = (uint32_t)((warp_m * 32 + mi * 16 + lm * 8 + lr) * 128);
    #pragma unroll
    for (int nj = 0; nj < 4; nj++)
        bRow[nj] = (uint32_t)((warp_n * 64 + nj * 16 + lm * 8 + lr) * 128);

    float acc[2][8][4];
    #pragma unroll
    for (int mi = 0; mi < 2; mi++)
        #pragma unroll
        for (int ni = 0; ni < 8; ni++)
            #pragma unroll
            for (int q = 0; q < 4; q++) acc[mi][ni][q] = 0.f;

    int s = 0, ph = 0;
    for (int i = 0; i < KTOT; i++){
        MBARRIER_WAIT_PARITY(sb + s * 8, ph);

        uint32_t stg = st0 + s * STAGE_BYTES;
        uint32_t sA  = stg;
        uint32_t sB  = stg + A_TILE_BYTES;

        #pragma unroll
        for (int ks = 0; ks < 4; ks++){
            uint32_t koff = ((uint32_t)(ks * 32) + g16) ^ xm;
            uint32_t a[2][4], b[8][2];
            #pragma unroll
            for (int mi = 0; mi < 2; mi++)
                LDSM_X4(a[mi][0], a[mi][1], a[mi][2], a[mi][3], sA + aRow[mi] + koff);
            #pragma unroll
            for (int nj = 0; nj < 4; nj++){
                uint32_t t0, t1, t2, t3;
                LDSM_X4(t0, t1, t2, t3, sB + bRow[nj] + koff);
                b[2*nj][0] = t0; b[2*nj][1] = t2;
                b[2*nj+1][0] = t1; b[2*nj+1][1] = t3;
            }
            if (ks == 3) MBARRIER_ARRIVE(sb + 64 + s * 8);   // all smem reads of this stage issued
            #pragma unroll
            for (int mi = 0; mi < 2; mi++)
                #pragma unroll
                for (int ni = 0; ni < 8; ni++)
                    MMA16816(acc[mi][ni], a[mi], b[ni]);
        }

        if (tid == 0 && i + NSTAGE < KTOT){
            MBARRIER_WAIT_PARITY(sb + 64 + s * 8, ph);
            int c = i + NSTAGE;
            uint32_t mbf = sb + s * 8;
            MBARRIER_EXPECT_TX(mbf, STAGE_BYTES);
            bulk_g2s(stg,                pA + (size_t)c * A_TILE_ELEMS, A_TILE_BYTES, mbf);
            bulk_g2s(stg + A_TILE_BYTES, pB + (size_t)c * B_TILE_ELEMS, B_TILE_BYTES, mbf);
        }
        if (++s == NSTAGE){ s = 0; ph ^= 1; }
    }

    // epilogue: direct STG.64 from accumulators
    int rowbase = mt * MT + warp_m * 32;
    int colbase = nt * NT + warp_n * 64;
    int rlo = lane >> 2, cq = (lane & 3) * 2;
    #pragma unroll
    for (int mi = 0; mi < 2; mi++){
        #pragma unroll
        for (int ni = 0; ni < 8; ni++){
            int r0 = rowbase + mi * 16 + rlo;
            int c  = colbase + ni * 8 + cq;
            float2 v0 = make_float2(acc[mi][ni][0], acc[mi][ni][1]);
            float2 v1 = make_float2(acc[mi][ni][2], acc[mi][ni][3]);
            *reinterpret_cast<float2*>(&out[(size_t)r0 * D_OUTF + c])       = v0;
            *reinterpret_cast<float2*>(&out[(size_t)(r0 + 8) * D_OUTF + c]) = v1;
        }
    }
}

// ---------------- launch ----------------
extern "C" void kernel_launch(void* const* d_in, const int* in_sizes, int n_in,
                              void* d_out, int out_size){
    const float* x   = (const float*)d_in[0];   // [8192, 4096]
    const float* tkw = (const float*)d_in[1];   // [8192, 4]
    const float* W   = (const float*)d_in[2];   // [4096, 4096]
    const float* qa  = (const float*)d_in[3];   // [4, 8, 4096]
    const float* qb  = (const float*)d_in[4];   // [4, 4096, 8]
    const float* sf  = (const float*)d_in[5];   // [4, 4096]
    float* out = (float*)d_out;                 // [8192, 4096]

    conv_x_kernel<<<(N_TOK * D_INF) / 256, 256>>>(x);
    conv_w_kernel<<<(D_OUTF * D_INF) / 256, 256>>>(W);
    lora_inter_kernel<<<N_TOK / 64, 256>>>(x, qa, tkw);
    pack_a_lora_kernel<<<(M_TILES * A_TILE_ELEMS) / 256, 256>>>();
    pack_b_lora_kernel<<<(N_TILES * B_TILE_ELEMS) / 256, 256>>>(qb, sf);

    cudaFuncSetAttribute(gemm_hmma_kernel,
                         cudaFuncAttributeMaxDynamicSharedMemorySize, SMEM_TOTAL);
    gemm_hmma_kernel<<<M_TILES * N_TILES, 256, SMEM_TOTAL>>>(out);
}

// round 8
// speedup vs baseline: 1.5798x; 1.0761x over previous
#include <cuda_runtime.h>
#include <cuda_fp16.h>
#include <cstdint>
#include <cstddef>

// ---------------- problem constants ----------------
#define N_TOK  8192
#define D_INF  4096
#define D_OUTF 4096

// GEMM tiling
#define MT   128
#define NT   128
#define BK   64
#define M_TILES 64      // 8192/128
#define N_TILES 32      // 4096/128
#define KTOT    65      // 64 main K-chunks + 1 LoRA chunk
#define NSTAGE  3

#define A_TILE_ELEMS (MT*BK)        // 8192 halves (16 KB)
#define B_TILE_ELEMS (NT*BK)        // 8192 halves (16 KB)
#define A_TILE_BYTES (A_TILE_ELEMS*2)
#define B_TILE_BYTES (B_TILE_ELEMS*2)
#define STAGE_BYTES  (A_TILE_BYTES + B_TILE_BYTES)       // 32768
#define SMEM_TOTAL   (1024 + 1024 + NSTAGE*STAGE_BYTES)  // 100352 -> 2 CTAs/SM

// ---------------- scratch (device globals; no cudaMalloc allowed) ----------------
__device__ __align__(1024) __half gA[(size_t)M_TILES*KTOT*A_TILE_ELEMS];  // x (fp16)
__device__ __align__(1024) __half gB[(size_t)N_TILES*KTOT*B_TILE_ELEMS];  // W (fp16)

// ---------------- PTX helpers (sm_100 baseline only) ----------------
__device__ __forceinline__ uint32_t smem_u32(const void* p){
    uint32_t a;
    asm("{ .reg .u64 t; cvta.to.shared.u64 t, %1; cvt.u32.u64 %0, t; }" : "=r"(a) : "l"(p));
    return a;
}
__device__ __forceinline__ uint32_t swz128(uint32_t b){ return b ^ ((b >> 3) & 0x70); }

#define MBARRIER_INIT(addr, cnt) \
    asm volatile("mbarrier.init.shared.b64 [%0], %1;" :: "r"(addr), "r"(cnt) : "memory")
#define MBARRIER_EXPECT_TX(addr, bytes) \
    asm volatile("mbarrier.arrive.expect_tx.shared.b64 _, [%0], %1;" :: "r"(addr), "r"(bytes) : "memory")
#define MBARRIER_ARRIVE(addr) \
    asm volatile("mbarrier.arrive.shared.b64 _, [%0];" :: "r"(addr) : "memory")
#define MBARRIER_WAIT_PARITY(addr, par) do {                                     \
    uint32_t _m = (addr); uint32_t _p = (par); uint32_t _d;                      \
    asm volatile("{\n\t.reg .pred p;\n\t"                                        \
        "mbarrier.try_wait.parity.acquire.cta.shared::cta.b64 p, [%1], %2;\n\t"  \
        "selp.b32 %0, 1, 0, p;\n\t}" : "=r"(_d) : "r"(_m), "r"(_p) : "memory");  \
    if (!_d) {                                                                   \
        asm volatile("{\n\t.reg .pred P1;\n\t"                                   \
        "W_%=:\n\t"                                                              \
        "mbarrier.try_wait.parity.acquire.cta.shared::cta.b64 P1, [%0], %1, 0x989680;\n\t" \
        "@P1 bra.uni D_%=;\n\t"                                                  \
        "bra.uni W_%=;\n\t"                                                      \
        "D_%=:\n\t}" :: "r"(_m), "r"(_p) : "memory");                            \
    }                                                                            \
} while (0)

__device__ __forceinline__ void bulk_g2s(uint32_t dst, const void* src, uint32_t bytes, uint32_t mbar){
    asm volatile("cp.async.bulk.shared::cta.global.mbarrier::complete_tx::bytes [%0], [%1], %2, [%3];"
        :: "r"(dst), "l"(src), "r"(bytes), "r"(mbar) : "memory");
}

#define LDSM_X4(r0, r1, r2, r3, addr) \
    asm volatile("ldmatrix.sync.aligned.m8n8.x4.shared.b16 {%0,%1,%2,%3}, [%4];" \
        : "=r"(r0), "=r"(r1), "=r"(r2), "=r"(r3) : "r"(addr))

#define MMA16816(d, a, b) \
    asm volatile("mma.sync.aligned.m16n8k16.row.col.f32.f16.f16.f32 " \
        "{%0,%1,%2,%3}, {%4,%5,%6,%7}, {%8,%9}, {%0,%1,%2,%3};" \
        : "+f"((d)[0]), "+f"((d)[1]), "+f"((d)[2]), "+f"((d)[3]) \
        : "r"((a)[0]), "r"((a)[1]), "r"((a)[2]), "r"((a)[3]), "r"((b)[0]), "r"((b)[1]))

__device__ __forceinline__ uint32_t pack2h(float a, float b){
    __half2 h = __floats2half2_rn(a, b);
    return *reinterpret_cast<uint32_t*>(&h);
}

// ---------------- fused prep (1 kernel): x conv | W conv | LoRA-B chunk ----------------
// Region A: x -> fp16 tiled+swizzled (8 elems/thread, float4 loads, uint4 store)
// Region B: W -> fp16 tiled+swizzled (same)
// Region C: gB LoRA chunk (scalar)
#define XBLK 16384      // (8192*4096/8)/256
#define WBLK 8192       // (4096*4096/8)/256
#define PBLK 1024       // (32*8192)/256

__global__ void __launch_bounds__(256) fused_prep_kernel(const float* __restrict__ x,
                                                         const float* __restrict__ W,
                                                         const float* __restrict__ qb,
                                                         const float* __restrict__ sf){
    int bid = blockIdx.x, tid = threadIdx.x;
    if (bid < XBLK){
        size_t t = (size_t)bid * 256 + tid;
        size_t base = t * 8;                              // k%8==0
        int n = (int)(base >> 12), k = (int)(base & 4095);
        float4 v0 = *reinterpret_cast<const float4*>(x + base);
        float4 v1 = *reinterpret_cast<const float4*>(x + base + 4);
        uint4 h;
        h.x = pack2h(v0.x, v0.y); h.y = pack2h(v0.z, v0.w);
        h.z = pack2h(v1.x, v1.y); h.w = pack2h(v1.z, v1.w);
        int mt = n >> 7, r = n & 127, kc = k >> 6, c = k & 63;
        size_t tile = (size_t)mt * KTOT + kc;
        uint32_t off = swz128((uint32_t)(r * 128 + c * 2));   // 16B-aligned -> stays aligned
        *reinterpret_cast<uint4*>(reinterpret_cast<char*>(&gA[tile * A_TILE_ELEMS]) + off) = h;
    } else if (bid < XBLK + WBLK){
        size_t t = (size_t)(bid - XBLK) * 256 + tid;
        size_t base = t * 8;
        int o = (int)(base >> 12), k = (int)(base & 4095);
        float4 v0 = *reinterpret_cast<const float4*>(W + base);
        float4 v1 = *reinterpret_cast<const float4*>(W + base + 4);
        uint4 h;
        h.x = pack2h(v0.x, v0.y); h.y = pack2h(v0.z, v0.w);
        h.z = pack2h(v1.x, v1.y); h.w = pack2h(v1.z, v1.w);
        int nt = o >> 7, r = o & 127, kc = k >> 6, c = k & 63;
        size_t tile = (size_t)nt * KTOT + kc;
        uint32_t off = swz128((uint32_t)(r * 128 + c * 2));
        *reinterpret_cast<uint4*>(reinterpret_cast<char*>(&gB[tile * B_TILE_ELEMS]) + off) = h;
    } else {
        int idx = (bid - XBLK - WBLK) * 256 + tid;        // < 32*8192
        int nt = idx >> 13, rem = idx & 8191;
        int r = rem >> 6, c = rem & 63;
        int o = nt * 128 + r;
        float v = 0.f;
        if (c < 32){
            int e = c >> 3, rr = c & 7;
            v = 0.1f * qb[((size_t)e * D_OUTF + o) * 8 + rr] * sf[(size_t)e * D_OUTF + o];
        }
        size_t tile = (size_t)nt * KTOT + 64;
        uint32_t off = swz128((uint32_t)(r * 128 + c * 2)) >> 1;
        gB[tile * B_TILE_ELEMS + off] = __float2half_rn(v);
    }
}

// ---------------- LoRA intermediate, writing packed gA LoRA chunk directly ----------------
// interw[n][j] = dot(x[n,:], qa[j,:]) * mask(tkw);  thread owns (row r, expert e=tid&3, 8 ranks)
__global__ void __launch_bounds__(256) lora_inter_kernel(const float* __restrict__ x,
                                                         const float* __restrict__ qa,
                                                         const float* __restrict__ tkw){
    __shared__ float sqa[32][33];
    __shared__ float sx[64][33];
    int n0  = blockIdx.x * 64;
    int tid = threadIdx.x;
    int r   = tid >> 2;            // 0..63
    int e   = tid & 3;             // expert
    int jq  = e * 8;               // col group 0,8,16,24
    float acc[8] = {0,0,0,0,0,0,0,0};
    for (int k0 = 0; k0 < D_INF; k0 += 32){
        for (int i = tid; i < 32*32; i += 256)
            sqa[i >> 5][i & 31] = qa[(size_t)(i >> 5) * D_INF + k0 + (i & 31)];
        for (int i = tid; i < 64*32; i += 256)
            sx[i >> 5][i & 31] = x[(size_t)(n0 + (i >> 5)) * D_INF + k0 + (i & 31)];
        __syncthreads();
        #pragma unroll
        for (int kk = 0; kk < 32; kk++){
            float xv = sx[r][kk];
            #pragma unroll
            for (int q = 0; q < 8; q++) acc[q] += xv * sqa[jq + q][kk];
        }
        __syncthreads();
    }
    int n = n0 + r;
    float w = tkw[n * 4 + e];
    w = (fabsf(w) > 1e-6f) ? w : 0.f;
    uint4 h;
    h.x = pack2h(acc[0]*w, acc[1]*w); h.y = pack2h(acc[2]*w, acc[3]*w);
    h.z = pack2h(acc[4]*w, acc[5]*w); h.w = pack2h(acc[6]*w, acc[7]*w);
    int mt = n >> 7, rr = n & 127;
    size_t tile = (size_t)mt * KTOT + 64;
    char* tb = reinterpret_cast<char*>(&gA[tile * A_TILE_ELEMS]);
    // data cols jq..jq+7 (16 B, aligned)
    *reinterpret_cast<uint4*>(tb + swz128((uint32_t)(rr * 128 + jq * 2))) = h;
    // zero cols 32+jq..39+jq
    *reinterpret_cast<uint4*>(tb + swz128((uint32_t)(rr * 128 + (32 + jq) * 2))) = make_uint4(0,0,0,0);
}

// ---------------- main GEMM: mma.sync fp16, 3-stage pipeline, 2 CTAs/SM ----------------
__global__ void __launch_bounds__(256, 2) gemm_hmma_kernel(float* __restrict__ out){
    extern __shared__ char smem_raw[];
    uint32_t raw = smem_u32(smem_raw);
    uint32_t sb  = (raw + 1023u) & ~1023u;        // barrier block
    uint32_t st0 = sb + 1024;                     // stage 0

    int tid = threadIdx.x, wid = tid >> 5, lane = tid & 31;
    int warp_m = wid & 3, warp_n = wid >> 2;      // 4x2 warp grid (32 rows x 64 cols each)
    int bid = blockIdx.x;
    int nt = bid >> 6, mt = bid & 63;             // panel raster: 64 M-tiles share B panel in L2

    const __half* pA = gA + (size_t)mt * (KTOT * A_TILE_ELEMS);
    const __half* pB = gB + (size_t)nt * (KTOT * B_TILE_ELEMS);

    // barriers: full[s] at sb + s*8, empty[s] at sb + 64 + s*8
    if (tid == 0){
        #pragma unroll
        for (int s = 0; s < NSTAGE; s++){
            MBARRIER_INIT(sb + s * 8, 1);
            MBARRIER_INIT(sb + 64 + s * 8, 256);
        }
        asm volatile("fence.proxy.async.shared::cta;" ::: "memory");
    }
    __syncthreads();

    if (tid == 0){
        #pragma unroll
        for (int s = 0; s < NSTAGE; s++){
            uint32_t st = st0 + s * STAGE_BYTES;
            uint32_t mbf = sb + s * 8;
            MBARRIER_EXPECT_TX(mbf, STAGE_BYTES);
            bulk_g2s(st,                pA + (size_t)s * A_TILE_ELEMS, A_TILE_BYTES, mbf);
            bulk_g2s(st + A_TILE_BYTES, pB + (size_t)s * B_TILE_ELEMS, B_TILE_BYTES, mbf);
        }
    }

    // ldmatrix per-lane address precomputation
    int lm = (lane >> 3) & 1;                     // row-half select within x4
    int lr = lane & 7;
    uint32_t g16 = (lane & 16);                   // k 16B-group select (0 or 16)
    uint32_t xm  = (uint32_t)(lr << 4);           // swizzle xor mask ((row&7)<<4)
    uint32_t aRow[2], bRow[4];
    #pragma unroll
    for (int mi = 0; mi < 2; mi++)
        aRow[mi] = (uint32_t)((warp_m * 32 + mi * 16 + lm * 8 + lr) * 128);
    #pragma unroll
    for (int nj = 0; nj < 4; nj++)
        bRow[nj] = (uint32_t)((warp_n * 64 + nj * 16 + lm * 8 + lr) * 128);

    float acc[2][8][4];
    #pragma unroll
    for (int mi = 0; mi < 2; mi++)
        #pragma unroll
        for (int ni = 0; ni < 8; ni++)
            #pragma unroll
            for (int q = 0; q < 4; q++) acc[mi][ni][q] = 0.f;

    int s = 0, ph = 0;
    for (int i = 0; i < KTOT; i++){
        MBARRIER_WAIT_PARITY(sb + s * 8, ph);

        uint32_t stg = st0 + s * STAGE_BYTES;
        uint32_t sA  = stg;
        uint32_t sB  = stg + A_TILE_BYTES;

        #pragma unroll
        for (int ks = 0; ks < 4; ks++){
            uint32_t koff = ((uint32_t)(ks * 32) + g16) ^ xm;
            uint32_t a[2][4], b[8][2];
            #pragma unroll
            for (int mi = 0; mi < 2; mi++)
                LDSM_X4(a[mi][0], a[mi][1], a[mi][2], a[mi][3], sA + aRow[mi] + koff);
            #pragma unroll
            for (int nj = 0; nj < 4; nj++){
                uint32_t t0, t1, t2, t3;
                LDSM_X4(t0, t1, t2, t3, sB + bRow[nj] + koff);
                b[2*nj][0] = t0; b[2*nj][1] = t2;
                b[2*nj+1][0] = t1; b[2*nj+1][1] = t3;
            }
            #pragma unroll
            for (int mi = 0; mi < 2; mi++)
                #pragma unroll
                for (int ni = 0; ni < 8; ni++)
                    MMA16816(acc[mi][ni], a[mi], b[ni]);
        }

        // arrive AFTER MMAs: MMA issue implies LDSM completion (register scoreboard),
        // so the producer can never overwrite a stage with reads in flight.
        MBARRIER_ARRIVE(sb + 64 + s * 8);

        if (tid == 0 && i + NSTAGE < KTOT){
            MBARRIER_WAIT_PARITY(sb + 64 + s * 8, ph);
            int c = i + NSTAGE;
            uint32_t mbf = sb + s * 8;
            MBARRIER_EXPECT_TX(mbf, STAGE_BYTES);
            bulk_g2s(stg,                pA + (size_t)c * A_TILE_ELEMS, A_TILE_BYTES, mbf);
            bulk_g2s(stg + A_TILE_BYTES, pB + (size_t)c * B_TILE_ELEMS, B_TILE_BYTES, mbf);
        }
        if (++s == NSTAGE){ s = 0; ph ^= 1; }
    }

    // epilogue: direct STG.64 from accumulators
    int rowbase = mt * MT + warp_m * 32;
    int colbase = nt * NT + warp_n * 64;
    int rlo = lane >> 2, cq = (lane & 3) * 2;
    #pragma unroll
    for (int mi = 0; mi < 2; mi++){
        #pragma unroll
        for (int ni = 0; ni < 8; ni++){
            int r0 = rowbase + mi * 16 + rlo;
            int c  = colbase + ni * 8 + cq;
            float2 v0 = make_float2(acc[mi][ni][0], acc[mi][ni][1]);
            float2 v1 = make_float2(acc[mi][ni][2], acc[mi][ni][3]);
            *reinterpret_cast<float2*>(&out[(size_t)r0 * D_OUTF + c])       = v0;
            *reinterpret_cast<float2*>(&out[(size_t)(r0 + 8) * D_OUTF + c]) = v1;
        }
    }
}

// ---------------- launch ----------------
extern "C" void kernel_launch(void* const* d_in, const int* in_sizes, int n_in,
                              void* d_out, int out_size){
    const float* x   = (const float*)d_in[0];   // [8192, 4096]
    const float* tkw = (const float*)d_in[1];   // [8192, 4]
    const float* W   = (const float*)d_in[2];   // [4096, 4096]
    const float* qa  = (const float*)d_in[3];   // [4, 8, 4096]
    const float* qb  = (const float*)d_in[4];   // [4, 4096, 8]
    const float* sf  = (const float*)d_in[5];   // [4, 4096]
    float* out = (float*)d_out;                 // [8192, 4096]

    fused_prep_kernel<<<XBLK + WBLK + PBLK, 256>>>(x, W, qb, sf);
    lora_inter_kernel<<<N_TOK / 64, 256>>>(x, qa, tkw);

    cudaFuncSetAttribute(gemm_hmma_kernel,
                         cudaFuncAttributeMaxDynamicSharedMemorySize, SMEM_TOTAL);
    gemm_hmma_kernel<<<M_TILES * N_TILES, 256, SMEM_TOTAL>>>(out);
}

// round 9
// speedup vs baseline: 1.6323x; 1.0332x over previous
#include <cuda_runtime.h>
#include <cuda_fp16.h>
#include <cstdint>
#include <cstddef>

// ---------------- problem constants ----------------
#define N_TOK  8192
#define D_INF  4096
#define D_OUTF 4096

// GEMM tiling
#define MT   128
#define NT   128
#define BK   64
#define M_TILES 64      // 8192/128
#define N_TILES 32      // 4096/128
#define KTOT    65      // 64 main K-chunks + 1 LoRA chunk
#define NSTAGE  3

#define A_TILE_ELEMS (MT*BK)        // 8192 halves (16 KB)
#define B_TILE_ELEMS (NT*BK)        // 8192 halves (16 KB)
#define A_TILE_BYTES (A_TILE_ELEMS*2)
#define B_TILE_BYTES (B_TILE_ELEMS*2)
#define STAGE_BYTES  (A_TILE_BYTES + B_TILE_BYTES)       // 32768
#define SMEM_TOTAL   (1024 + 1024 + NSTAGE*STAGE_BYTES)  // 100352 -> 2 CTAs/SM

// ---------------- scratch (device globals; no cudaMalloc allowed) ----------------
__device__ __align__(1024) __half gA[(size_t)M_TILES*KTOT*A_TILE_ELEMS];  // x (fp16)
__device__ __align__(1024) __half gB[(size_t)N_TILES*KTOT*B_TILE_ELEMS];  // W (fp16)

// ---------------- PTX helpers (sm_100 baseline only) ----------------
__device__ __forceinline__ uint32_t smem_u32(const void* p){
    uint32_t a;
    asm("{ .reg .u64 t; cvta.to.shared.u64 t, %1; cvt.u32.u64 %0, t; }" : "=r"(a) : "l"(p));
    return a;
}
__device__ __forceinline__ uint32_t swz128(uint32_t b){ return b ^ ((b >> 3) & 0x70); }

#define MBARRIER_INIT(addr, cnt) \
    asm volatile("mbarrier.init.shared.b64 [%0], %1;" :: "r"(addr), "r"(cnt) : "memory")
#define MBARRIER_EXPECT_TX(addr, bytes) \
    asm volatile("mbarrier.arrive.expect_tx.shared.b64 _, [%0], %1;" :: "r"(addr), "r"(bytes) : "memory")
#define MBARRIER_ARRIVE(addr) \
    asm volatile("mbarrier.arrive.shared.b64 _, [%0];" :: "r"(addr) : "memory")
#define MBARRIER_WAIT_PARITY(addr, par) do {                                     \
    uint32_t _m = (addr); uint32_t _p = (par); uint32_t _d;                      \
    asm volatile("{\n\t.reg .pred p;\n\t"                                        \
        "mbarrier.try_wait.parity.acquire.cta.shared::cta.b64 p, [%1], %2;\n\t"  \
        "selp.b32 %0, 1, 0, p;\n\t}" : "=r"(_d) : "r"(_m), "r"(_p) : "memory");  \
    if (!_d) {                                                                   \
        asm volatile("{\n\t.reg .pred P1;\n\t"                                   \
        "W_%=:\n\t"                                                              \
        "mbarrier.try_wait.parity.acquire.cta.shared::cta.b64 P1, [%0], %1, 0x989680;\n\t" \
        "@P1 bra.uni D_%=;\n\t"                                                  \
        "bra.uni W_%=;\n\t"                                                      \
        "D_%=:\n\t}" :: "r"(_m), "r"(_p) : "memory");                            \
    }                                                                            \
} while (0)

__device__ __forceinline__ void bulk_g2s(uint32_t dst, const void* src, uint32_t bytes, uint32_t mbar){
    asm volatile("cp.async.bulk.shared::cta.global.mbarrier::complete_tx::bytes [%0], [%1], %2, [%3];"
        :: "r"(dst), "l"(src), "r"(bytes), "r"(mbar) : "memory");
}

#define LDSM_X4(r0, r1, r2, r3, addr) \
    asm volatile("ldmatrix.sync.aligned.m8n8.x4.shared.b16 {%0,%1,%2,%3}, [%4];" \
        : "=r"(r0), "=r"(r1), "=r"(r2), "=r"(r3) : "r"(addr))

#define MMA16816(d, a, b) \
    asm volatile("mma.sync.aligned.m16n8k16.row.col.f32.f16.f16.f32 " \
        "{%0,%1,%2,%3}, {%4,%5,%6,%7}, {%8,%9}, {%0,%1,%2,%3};" \
        : "+f"((d)[0]), "+f"((d)[1]), "+f"((d)[2]), "+f"((d)[3]) \
        : "r"((a)[0]), "r"((a)[1]), "r"((a)[2]), "r"((a)[3]), "r"((b)[0]), "r"((b)[1]))

__device__ __forceinline__ uint32_t pack2h(float a, float b){
    __half2 h = __floats2half2_rn(a, b);
    return *reinterpret_cast<uint32_t*>(&h);
}

// ---------------- fused prep (1 kernel): x conv | W conv | LoRA-B chunk ----------------
#define XBLK 16384      // (8192*4096/8)/256
#define WBLK 8192       // (4096*4096/8)/256
#define PBLK 1024       // (32*8192)/256

__global__ void __launch_bounds__(256) fused_prep_kernel(const float* __restrict__ x,
                                                         const float* __restrict__ W,
                                                         const float* __restrict__ qb,
                                                         const float* __restrict__ sf){
    int bid = blockIdx.x, tid = threadIdx.x;
    if (bid < XBLK){
        size_t t = (size_t)bid * 256 + tid;
        size_t base = t * 8;                              // k%8==0
        int n = (int)(base >> 12), k = (int)(base & 4095);
        float4 v0 = *reinterpret_cast<const float4*>(x + base);
        float4 v1 = *reinterpret_cast<const float4*>(x + base + 4);
        uint4 h;
        h.x = pack2h(v0.x, v0.y); h.y = pack2h(v0.z, v0.w);
        h.z = pack2h(v1.x, v1.y); h.w = pack2h(v1.z, v1.w);
        int mt = n >> 7, r = n & 127, kc = k >> 6, c = k & 63;
        size_t tile = (size_t)mt * KTOT + kc;
        uint32_t off = swz128((uint32_t)(r * 128 + c * 2));   // 16B-aligned -> stays aligned
        *reinterpret_cast<uint4*>(reinterpret_cast<char*>(&gA[tile * A_TILE_ELEMS]) + off) = h;
    } else if (bid < XBLK + WBLK){
        size_t t = (size_t)(bid - XBLK) * 256 + tid;
        size_t base = t * 8;
        int o = (int)(base >> 12), k = (int)(base & 4095);
        float4 v0 = *reinterpret_cast<const float4*>(W + base);
        float4 v1 = *reinterpret_cast<const float4*>(W + base + 4);
        uint4 h;
        h.x = pack2h(v0.x, v0.y); h.y = pack2h(v0.z, v0.w);
        h.z = pack2h(v1.x, v1.y); h.w = pack2h(v1.z, v1.w);
        int nt = o >> 7, r = o & 127, kc = k >> 6, c = k & 63;
        size_t tile = (size_t)nt * KTOT + kc;
        uint32_t off = swz128((uint32_t)(r * 128 + c * 2));
        *reinterpret_cast<uint4*>(reinterpret_cast<char*>(&gB[tile * B_TILE_ELEMS]) + off) = h;
    } else {
        int idx = (bid - XBLK - WBLK) * 256 + tid;        // < 32*8192
        int nt = idx >> 13, rem = idx & 8191;
        int r = rem >> 6, c = rem & 63;
        int o = nt * 128 + r;
        float v = 0.f;
        if (c < 32){
            int e = c >> 3, rr = c & 7;
            v = 0.1f * qb[((size_t)e * D_OUTF + o) * 8 + rr] * sf[(size_t)e * D_OUTF + o];
        }
        size_t tile = (size_t)nt * KTOT + 64;
        uint32_t off = swz128((uint32_t)(r * 128 + c * 2)) >> 1;
        gB[tile * B_TILE_ELEMS + off] = __float2half_rn(v);
    }
}

// ---------------- LoRA intermediate, writing packed gA LoRA chunk directly ----------------
__global__ void __launch_bounds__(256) lora_inter_kernel(const float* __restrict__ x,
                                                         const float* __restrict__ qa,
                                                         const float* __restrict__ tkw){
    __shared__ float sqa[32][33];
    __shared__ float sx[64][33];
    int n0  = blockIdx.x * 64;
    int tid = threadIdx.x;
    int r   = tid >> 2;            // 0..63
    int e   = tid & 3;             // expert
    int jq  = e * 8;               // col group 0,8,16,24
    float acc[8] = {0,0,0,0,0,0,0,0};
    for (int k0 = 0; k0 < D_INF; k0 += 32){
        for (int i = tid; i < 32*32; i += 256)
            sqa[i >> 5][i & 31] = qa[(size_t)(i >> 5) * D_INF + k0 + (i & 31)];
        for (int i = tid; i < 64*32; i += 256)
            sx[i >> 5][i & 31] = x[(size_t)(n0 + (i >> 5)) * D_INF + k0 + (i & 31)];
        __syncthreads();
        #pragma unroll
        for (int kk = 0; kk < 32; kk++){
            float xv = sx[r][kk];
            #pragma unroll
            for (int q = 0; q < 8; q++) acc[q] += xv * sqa[jq + q][kk];
        }
        __syncthreads();
    }
    int n = n0 + r;
    float w = tkw[n * 4 + e];
    w = (fabsf(w) > 1e-6f) ? w : 0.f;
    uint4 h;
    h.x = pack2h(acc[0]*w, acc[1]*w); h.y = pack2h(acc[2]*w, acc[3]*w);
    h.z = pack2h(acc[4]*w, acc[5]*w); h.w = pack2h(acc[6]*w, acc[7]*w);
    int mt = n >> 7, rr = n & 127;
    size_t tile = (size_t)mt * KTOT + 64;
    char* tb = reinterpret_cast<char*>(&gA[tile * A_TILE_ELEMS]);
    *reinterpret_cast<uint4*>(tb + swz128((uint32_t)(rr * 128 + jq * 2))) = h;
    *reinterpret_cast<uint4*>(tb + swz128((uint32_t)(rr * 128 + (32 + jq) * 2))) = make_uint4(0,0,0,0);
}

// ---------------- main GEMM: warp-specialized producer (9 warps), 3-stage ring ----------------
__global__ void __launch_bounds__(288, 2) gemm_hmma_kernel(float* __restrict__ out){
    extern __shared__ char smem_raw[];
    uint32_t raw = smem_u32(smem_raw);
    uint32_t sb  = (raw + 1023u) & ~1023u;        // barrier block
    uint32_t st0 = sb + 1024;                     // stage 0

    int tid = threadIdx.x, wid = tid >> 5, lane = tid & 31;
    int bid = blockIdx.x;
    int nt = bid >> 6, mt = bid & 63;             // panel raster: 64 M-tiles share B panel in L2

    const __half* pA = gA + (size_t)mt * (KTOT * A_TILE_ELEMS);
    const __half* pB = gB + (size_t)nt * (KTOT * B_TILE_ELEMS);

    // barriers: full[s] at sb + s*8, empty[s] at sb + 64 + s*8 (empty counts = 256 compute threads)
    if (tid == 0){
        #pragma unroll
        for (int s = 0; s < NSTAGE; s++){
            MBARRIER_INIT(sb + s * 8, 1);
            MBARRIER_INIT(sb + 64 + s * 8, 256);
        }
        asm volatile("fence.proxy.async.shared::cta;" ::: "memory");
    }
    __syncthreads();

    if (wid == 8){
        // ---- producer warp: one thread drives the whole TMA ring ----
        if (lane == 0){
            #pragma unroll
            for (int s = 0; s < NSTAGE; s++){
                uint32_t st = st0 + s * STAGE_BYTES;
                uint32_t mbf = sb + s * 8;
                MBARRIER_EXPECT_TX(mbf, STAGE_BYTES);
                bulk_g2s(st,                pA + (size_t)s * A_TILE_ELEMS, A_TILE_BYTES, mbf);
                bulk_g2s(st + A_TILE_BYTES, pB + (size_t)s * B_TILE_ELEMS, B_TILE_BYTES, mbf);
            }
            int s = 0, ph = 0;
            for (int c = NSTAGE; c < KTOT; c++){
                MBARRIER_WAIT_PARITY(sb + 64 + s * 8, ph);    // stage drained by consumers
                uint32_t st = st0 + s * STAGE_BYTES;
                uint32_t mbf = sb + s * 8;
                MBARRIER_EXPECT_TX(mbf, STAGE_BYTES);
                bulk_g2s(st,                pA + (size_t)c * A_TILE_ELEMS, A_TILE_BYTES, mbf);
                bulk_g2s(st + A_TILE_BYTES, pB + (size_t)c * B_TILE_ELEMS, B_TILE_BYTES, mbf);
                if (++s == NSTAGE){ s = 0; ph ^= 1; }
            }
        }
        return;
    }

    // ---- compute warps 0..7 ----
    int warp_m = wid & 3, warp_n = wid >> 2;      // 4x2 warp grid (32 rows x 64 cols each)

    int lm = (lane >> 3) & 1;                     // row-half select within x4
    int lr = lane & 7;
    uint32_t g16 = (lane & 16);                   // k 16B-group select (0 or 16)
    uint32_t xm  = (uint32_t)(lr << 4);           // swizzle xor mask ((row&7)<<4)
    uint32_t aRow[2], bRow[4];
    #pragma unroll
    for (int mi = 0; mi < 2; mi++)
        aRow[mi] = (uint32_t)((warp_m * 32 + mi * 16 + lm * 8 + lr) * 128);
    #pragma unroll
    for (int nj = 0; nj < 4; nj++)
        bRow[nj] = (uint32_t)((warp_n * 64 + nj * 16 + lm * 8 + lr) * 128);

    float acc[2][8][4];
    #pragma unroll
    for (int mi = 0; mi < 2; mi++)
        #pragma unroll
        for (int ni = 0; ni < 8; ni++)
            #pragma unroll
            for (int q = 0; q < 4; q++) acc[mi][ni][q] = 0.f;

    int s = 0, ph = 0;
    for (int i = 0; i < KTOT; i++){
        MBARRIER_WAIT_PARITY(sb + s * 8, ph);

        uint32_t stg = st0 + s * STAGE_BYTES;
        uint32_t sA  = stg;
        uint32_t sB  = stg + A_TILE_BYTES;

        #pragma unroll
        for (int ks = 0; ks < 4; ks++){
            uint32_t koff = ((uint32_t)(ks * 32) + g16) ^ xm;
            uint32_t a[2][4], b[8][2];
            #pragma unroll
            for (int mi = 0; mi < 2; mi++)
                LDSM_X4(a[mi][0], a[mi][1], a[mi][2], a[mi][3], sA + aRow[mi] + koff);
            #pragma unroll
            for (int nj = 0; nj < 4; nj++){
                uint32_t t0, t1, t2, t3;
                LDSM_X4(t0, t1, t2, t3, sB + bRow[nj] + koff);
                b[2*nj][0] = t0; b[2*nj][1] = t2;
                b[2*nj+1][0] = t1; b[2*nj+1][1] = t3;
            }
            #pragma unroll
            for (int mi = 0; mi < 2; mi++)
                #pragma unroll
                for (int ni = 0; ni < 8; ni++)
                    MMA16816(acc[mi][ni], a[mi], b[ni]);
        }

        // arrive AFTER MMAs: MMA issue implies LDSM completion (register scoreboard),
        // so the producer can never overwrite a stage with reads in flight.
        MBARRIER_ARRIVE(sb + 64 + s * 8);
        if (++s == NSTAGE){ s = 0; ph ^= 1; }
    }

    // epilogue: direct STG.64 from accumulators
    int rowbase = mt * MT + warp_m * 32;
    int colbase = nt * NT + warp_n * 64;
    int rlo = lane >> 2, cq = (lane & 3) * 2;
    #pragma unroll
    for (int mi = 0; mi < 2; mi++){
        #pragma unroll
        for (int ni = 0; ni < 8; ni++){
            int r0 = rowbase + mi * 16 + rlo;
            int c  = colbase + ni * 8 + cq;
            float2 v0 = make_float2(acc[mi][ni][0], acc[mi][ni][1]);
            float2 v1 = make_float2(acc[mi][ni][2], acc[mi][ni][3]);
            *reinterpret_cast<float2*>(&out[(size_t)r0 * D_OUTF + c])       = v0;
            *reinterpret_cast<float2*>(&out[(size_t)(r0 + 8) * D_OUTF + c]) = v1;
        }
    }
}

// ---------------- launch ----------------
extern "C" void kernel_launch(void* const* d_in, const int* in_sizes, int n_in,
                              void* d_out, int out_size){
    const float* x   = (const float*)d_in[0];   // [8192, 4096]
    const float* tkw = (const float*)d_in[1];   // [8192, 4]
    const float* W   = (const float*)d_in[2];   // [4096, 4096]
    const float* qa  = (const float*)d_in[3];   // [4, 8, 4096]
    const float* qb  = (const float*)d_in[4];   // [4, 4096, 8]
    const float* sf  = (const float*)d_in[5];   // [4, 4096]
    float* out = (float*)d_out;                 // [8192, 4096]

    fused_prep_kernel<<<XBLK + WBLK + PBLK, 256>>>(x, W, qb, sf);
    lora_inter_kernel<<<N_TOK / 64, 256>>>(x, qa, tkw);

    cudaFuncSetAttribute(gemm_hmma_kernel,
                         cudaFuncAttributeMaxDynamicSharedMemorySize, SMEM_TOTAL);
    gemm_hmma_kernel<<<M_TILES * N_TILES, 288, SMEM_TOTAL>>>(out);
}